// round 1
// baseline (speedup 1.0000x reference)
#include <cuda_runtime.h>
#include <float.h>

// RoIPool: features (N=2, C=256, H=50, W=50) fp32, rois (K=256, 5) fp32
// -> out (K, C, 7, 7) fp32.
// One thread per output element; flat index == output linear index so STG is
// fully coalesced. A warp covers ~32 consecutive bins of one (k,c) pair, so
// all its LDGs hit a <=17x17 window of one channel plane (L1-resident).

#define POOLED 7
#define SCALE_F 0.0625f

__global__ void __launch_bounds__(256) roipool_kernel(
    const float* __restrict__ features,
    const float* __restrict__ rois,
    float* __restrict__ out,
    int C, int H, int W, int total)
{
    int idx = blockIdx.x * blockDim.x + threadIdx.x;
    if (idx >= total) return;

    int pw = idx % POOLED;
    int ph = (idx / POOLED) % POOLED;
    int c  = (idx / (POOLED * POOLED)) % C;
    int k  = idx / (POOLED * POOLED * C);

    // roi params (K=256 * 5 floats: stays hot in L1/L2; redundant across c but cheap)
    const float* r = rois + (size_t)k * 5;
    int b  = (int)r[0];
    int x1 = (int)floorf(r[1] * SCALE_F + 0.5f);
    int y1 = (int)floorf(r[2] * SCALE_F + 0.5f);
    int x2 = (int)floorf(r[3] * SCALE_F + 0.5f);
    int y2 = (int)floorf(r[4] * SCALE_F + 0.5f);

    float roi_w = (float)max(x2 - x1 + 1, 1);
    float roi_h = (float)max(y2 - y1 + 1, 1);
    float bin_w = roi_w * (1.0f / POOLED);
    float bin_h = roi_h * (1.0f / POOLED);

    int wstart = min(max((int)floorf((float)pw        * bin_w) + x1, 0), W);
    int wend   = min(max((int)ceilf ((float)(pw + 1)  * bin_w) + x1, 0), W);
    int hstart = min(max((int)floorf((float)ph        * bin_h) + y1, 0), H);
    int hend   = min(max((int)ceilf ((float)(ph + 1)  * bin_h) + y1, 0), H);

    float m;
    if (hend <= hstart || wend <= wstart) {
        m = 0.0f;  // empty bin -> 0 per reference
    } else {
        m = -FLT_MAX;
        const float* plane = features + ((size_t)b * C + c) * (size_t)(H * W);
        for (int h = hstart; h < hend; ++h) {
            const float* row = plane + h * W;
            #pragma unroll 4
            for (int w = wstart; w < wend; ++w) {
                m = fmaxf(m, __ldg(row + w));
            }
        }
    }
    out[idx] = m;
}

extern "C" void kernel_launch(void* const* d_in, const int* in_sizes, int n_in,
                              void* d_out, int out_size)
{
    const float* features = (const float*)d_in[0];
    const float* rois     = (const float*)d_in[1];
    float* out            = (float*)d_out;

    const int C = 256, H = 50, W = 50;
    const int K = in_sizes[1] / 5;            // 256
    const int total = K * C * POOLED * POOLED; // 3,211,264 == out_size

    int threads = 256;
    int blocks = (total + threads - 1) / threads;
    roipool_kernel<<<blocks, threads>>>(features, rois, out, C, H, W, total);
}

// round 2
// speedup vs baseline: 1.2372x; 1.2372x over previous
#include <cuda_runtime.h>
#include <float.h>

// RoIPool: features (N=2, C=256, H=50, W=50) fp32, rois (K=256, 5) fp32
// -> out (K, C, 7, 7) fp32.
//
// R1 showed issue/ALU-bound (alu 48%, fma 25%, dram 2%). This version kills
// the per-thread roi setup: grid=(49, K); each block handles 256 consecutive
// (c,bin) outputs of one roi. The 49 bin configs are computed once per block
// into smem (packed counts + precomputed base offset), so per-thread work is
// 1 LDS pair + divide-by-49 + the max window + coalesced STG.

#define POOLED 7
#define SCALE_F 0.0625f
#define NBINS 49            // 7*7
#define CH 256
#define FH 50
#define FW 50
#define PLANE (FH * FW)     // 2500

__global__ void __launch_bounds__(256) roipool_kernel(
    const float* __restrict__ features,
    const float* __restrict__ rois,
    float* __restrict__ out)
{
    __shared__ unsigned s_cfg[NBINS];   // wcount<<8 | hcount (0 if empty)
    __shared__ int      s_base[NBINS];  // b*C*PLANE + hstart*FW + wstart

    const int k = blockIdx.y;
    const int t = threadIdx.x;

    if (t < NBINS) {
        const float* r = rois + k * 5;
        int b  = (int)r[0];
        int x1 = (int)floorf(r[1] * SCALE_F + 0.5f);
        int y1 = (int)floorf(r[2] * SCALE_F + 0.5f);
        int x2 = (int)floorf(r[3] * SCALE_F + 0.5f);
        int y2 = (int)floorf(r[4] * SCALE_F + 0.5f);

        float bin_w = (float)max(x2 - x1 + 1, 1) * (1.0f / POOLED);
        float bin_h = (float)max(y2 - y1 + 1, 1) * (1.0f / POOLED);

        int ph = t / POOLED;
        int pw = t - ph * POOLED;

        int wstart = min(max((int)floorf((float)pw       * bin_w) + x1, 0), FW);
        int wend   = min(max((int)ceilf ((float)(pw + 1) * bin_w) + x1, 0), FW);
        int hstart = min(max((int)floorf((float)ph       * bin_h) + y1, 0), FH);
        int hend   = min(max((int)ceilf ((float)(ph + 1) * bin_h) + y1, 0), FH);

        int hc = hend - hstart;
        int wc = wend - wstart;
        unsigned cfg = (hc > 0 && wc > 0) ? (unsigned)((wc << 8) | hc) : 0u;
        s_cfg[t]  = cfg;
        s_base[t] = b * (CH * PLANE) + hstart * FW + wstart;
    }
    __syncthreads();

    // j in [0, 12544): output element (c*49 + bin) of roi k
    const int j   = blockIdx.x * 256 + t;
    const int c   = j / NBINS;          // magic-number divide (const divisor)
    const int bin = j - c * NBINS;

    const unsigned cfg = s_cfg[bin];
    const int hc = (int)(cfg & 0xffu);
    const int wc = (int)(cfg >> 8);

    float m = 0.0f;                      // empty bin -> 0 per reference
    if (cfg) {
        const float* p = features + s_base[bin] + c * PLANE;
        m = -FLT_MAX;
        for (int h = 0; h < hc; ++h) {
            const float* row = p + h * FW;
            #pragma unroll 4
            for (int w = 0; w < wc; ++w) {
                m = fmaxf(m, __ldg(row + w));
            }
        }
    }
    out[(size_t)k * (CH * NBINS) + j] = m;
}

extern "C" void kernel_launch(void* const* d_in, const int* in_sizes, int n_in,
                              void* d_out, int out_size)
{
    const float* features = (const float*)d_in[0];
    const float* rois     = (const float*)d_in[1];
    float* out            = (float*)d_out;

    const int K = in_sizes[1] / 5;   // 256
    dim3 grid(NBINS, K);             // 49 x 256 blocks, 256 threads each
    roipool_kernel<<<grid, 256>>>(features, rois, out);
}